// round 3
// baseline (speedup 1.0000x reference)
#include <cuda_runtime.h>
#include <cstdint>

// ---------------------------------------------------------------------------
// TripletLoss, single fused persistent kernel.
//   B=384, D=256, C=48. JAX-exact gumbel via threefry2x32 (partitionable path,
//   bits = x0^x1, key=[0,42]), evaluated on demand at semi-hard sites only.
//   Phase 1: tiled 384x384 distance matrix (12x12 tiles of 32x32, K-chunked).
//   Phase 2: grid barrier (144 blocks, single wave on 148 SMs).
//   Phase 3: per-block pair scan + gumbel argmax + accumulation.
//   Phase 4: grid barrier, block 0 writes the scalar.
// ---------------------------------------------------------------------------

#define B 384
#define D 256
#define MARGIN 0.2f
#define TINYF 1.17549435e-38f
#define NBLK 144
#define NTHR 512
#define TILE 32

// ---- persistent device state ------------------------------------------------
__device__ float    g_dist[B * B];
__device__ float    g_total;
__device__ int      g_count;
__device__ unsigned g_barcnt = 0;
__device__ volatile unsigned g_sense = 0;

// ---- threefry2x32, JAX schedule, key = [0, 42] -------------------------------
__device__ __forceinline__ uint32_t rotl32(uint32_t x, int d) {
    return __funnelshift_l(x, x, d);
}

__device__ __forceinline__ float gumbel_at(uint32_t n) {
    // counter = (0, n) since n < 384^3 < 2^32 ; key = [0, 42]
    const uint32_t k0 = 0u, k1 = 42u;
    const uint32_t k2 = k0 ^ k1 ^ 0x1BD11BDAu;
    uint32_t x0 = 0u + k0, x1 = n + k1;
#define TF_RND(r) { x0 += x1; x1 = rotl32(x1, (r)); x1 ^= x0; }
    TF_RND(13) TF_RND(15) TF_RND(26) TF_RND(6)
    x0 += k1; x1 += k2 + 1u;
    TF_RND(17) TF_RND(29) TF_RND(16) TF_RND(24)
    x0 += k2; x1 += k0 + 2u;
    TF_RND(13) TF_RND(15) TF_RND(26) TF_RND(6)
    x0 += k0; x1 += k1 + 3u;
    TF_RND(17) TF_RND(29) TF_RND(16) TF_RND(24)
    x0 += k1; x1 += k2 + 4u;
    TF_RND(13) TF_RND(15) TF_RND(26) TF_RND(6)
    x0 += k2; x1 += k0 + 5u;
#undef TF_RND
    uint32_t bits = x0 ^ x1;   // partitionable 32-bit draw
    float f = __uint_as_float((bits >> 9) | 0x3f800000u) - 1.0f;
    float u = fmaxf(TINYF, f + TINYF);
    return -logf(-logf(u));
}

// ---- sense-reversing grid barrier (all blocks resident: 144 <= 148 SMs) -----
__device__ __forceinline__ void grid_barrier() {
    __syncthreads();
    __threadfence();
    if (threadIdx.x == 0) {
        unsigned s = g_sense;
        if (atomicAdd(&g_barcnt, 1u) == gridDim.x - 1) {
            atomicExch(&g_barcnt, 0u);
            __threadfence();
            g_sense = s ^ 1u;
        } else {
            while (g_sense == s) { }
        }
    }
    __syncthreads();
}

// ---- the fused kernel --------------------------------------------------------
__global__ void __launch_bounds__(NTHR)
k_fused(const float* __restrict__ f, const int* __restrict__ labels,
        const int* __restrict__ epoch, float* __restrict__ out) {
    __shared__ float As[TILE][TILE + 1];
    __shared__ float Bs[TILE][TILE + 1];
    __shared__ int   s_lab[B];
    __shared__ int   s_pairs[1024];
    __shared__ int   s_np;
    __shared__ float s_val[16];
    __shared__ int   s_idx[16];
    __shared__ int   s_anyv[16];

    const int tid = threadIdx.x;
    const int bid = blockIdx.x;

    if (bid == 0 && tid == 0) { g_total = 0.0f; g_count = 0; }
    if (tid < B) s_lab[tid] = labels[tid];
    if (tid == 0) s_np = 0;

    // ---- phase 1: distance tile (32x32), K chunked by 32 ----
    {
        const int by = bid / 12, bx = bid % 12;
        const int i0 = by * TILE, j0 = bx * TILE;
        const int lr = tid >> 5;          // load row 0..15 (and +16)
        const int lc = tid & 31;          // load col
        const int r0 = tid >> 5;          // output rows r0 and r0+16, col c0
        const int c0 = tid & 31;
        float acc0 = 0.0f, acc1 = 0.0f;

        for (int kk = 0; kk < D; kk += TILE) {
            As[lr][lc]      = f[(i0 + lr)      * D + kk + lc];
            As[lr + 16][lc] = f[(i0 + lr + 16) * D + kk + lc];
            Bs[lr][lc]      = f[(j0 + lr)      * D + kk + lc];
            Bs[lr + 16][lc] = f[(j0 + lr + 16) * D + kk + lc];
            __syncthreads();
#pragma unroll
            for (int k2 = 0; k2 < TILE; k2++) {
                float bv = Bs[c0][k2];                 // conflict-free (pitch 33)
                float d0 = As[r0][k2] - bv;            // broadcast
                float d1 = As[r0 + 16][k2] - bv;
                acc0 += d0 * d0;
                acc1 += d1 * d1;
            }
            __syncthreads();
        }
        g_dist[(i0 + r0)      * B + j0 + c0] = sqrtf(fmaxf(acc0, 1e-11f));
        g_dist[(i0 + r0 + 16) * B + j0 + c0] = sqrtf(fmaxf(acc1, 1e-11f));
    }

    grid_barrier();

    // ---- phase 3: pair scan (384*384 == 144 * 1024 combos) ----
#pragma unroll
    for (int e = 0; e < 2; e++) {
        int idx = bid * 1024 + tid + e * NTHR;
        int i = idx / B, p = idx - i * B;
        if (p > i && s_lab[i] == s_lab[p]) {
            int slot = atomicAdd(&s_np, 1);
            s_pairs[slot] = (i << 16) | p;
        }
    }
    __syncthreads();

    // ---- per-pair gumbel argmax ----
    const bool semi_mode = (epoch[0] > 3);
    const int lane = tid & 31, w = tid >> 5;
    float bl_total = 0.0f;
    int   bl_count = 0;
    const int np = s_np;

    for (int q = 0; q < np; q++) {
        const int code = s_pairs[q];
        const int i = code >> 16, p = code & 0xffff;
        const float dpos = g_dist[i * B + p];

        float score = -3.0e38f;
        int   ix = tid;
        bool  semi = false;
        if (tid < B) {
            const int k = tid;
            const float dik = g_dist[i * B + k];
            const bool neg = (s_lab[k] != s_lab[i]);
            semi = semi_mode ? (neg && dik > dpos && dik < dpos + MARGIN) : neg;
            if (semi) {
                float base = semi_mode ? -logf(dik) : 0.0f;
                score = base + gumbel_at(((uint32_t)i * B + p) * B + k);
            }
        }
        // warp argmax, first-index tie break
#pragma unroll
        for (int off = 16; off; off >>= 1) {
            float ov = __shfl_down_sync(0xffffffffu, score, off);
            int   oi = __shfl_down_sync(0xffffffffu, ix, off);
            if (ov > score || (ov == score && oi < ix)) { score = ov; ix = oi; }
        }
        unsigned anyw = __ballot_sync(0xffffffffu, semi);
        if (lane == 0) { s_val[w] = score; s_idx[w] = ix; s_anyv[w] = (anyw != 0); }
        __syncthreads();

        if (tid == 0) {
            float bv = s_val[0]; int bi = s_idx[0]; int any = s_anyv[0];
#pragma unroll
            for (int ww = 1; ww < 16; ww++) {
                any |= s_anyv[ww];
                if (s_val[ww] > bv || (s_val[ww] == bv && s_idx[ww] < bi)) {
                    bv = s_val[ww]; bi = s_idx[ww];
                }
            }
            if (any) {
                bl_total += fmaxf(dpos - g_dist[i * B + bi] + MARGIN, 0.0f);
                bl_count += 1;
            }
        }
        __syncthreads();
    }

    if (tid == 0 && bl_count > 0) {
        atomicAdd(&g_total, bl_total);
        atomicAdd(&g_count, bl_count);
    }

    grid_barrier();

    if (bid == 0 && tid == 0) {
        int c = g_count;
        out[0] = (c > 0) ? (g_total / (float)c) : 0.0f;
    }
}

// ---- launch ------------------------------------------------------------------
extern "C" void kernel_launch(void* const* d_in, const int* in_sizes, int n_in,
                              void* d_out, int out_size) {
    const float* feat   = (const float*)d_in[0];
    const int*   labels = (const int*)d_in[1];
    const int*   epoch  = (const int*)d_in[2];
    float* out = (float*)d_out;

    k_fused<<<NBLK, NTHR>>>(feat, labels, epoch, out);
}

// round 4
// speedup vs baseline: 1.0550x; 1.0550x over previous
#include <cuda_runtime.h>
#include <cstdint>

// ---------------------------------------------------------------------------
// TripletLoss, single fused persistent kernel.
//   B=384, D=256, C=48. JAX-exact gumbel via threefry2x32 (partitionable path,
//   bits = x0^x1, key=[0,42]), evaluated on demand at semi-hard sites only.
//   Phase 1: tiled 384x384 distance matrix (12x12 tiles of 32x32, K-chunked).
//   Phase 2: grid barrier (144 blocks, single wave on 148 SMs).
//   Phase 3: per-block pair scan + gumbel argmax + accumulation.
//   Phase 4: grid barrier, block 0 writes the scalar.
// ---------------------------------------------------------------------------

#define B 384
#define D 256
#define MARGIN 0.2f
#define TINYF 1.17549435e-38f
#define NBLK 144
#define NTHR 512
#define TILE 32

// ---- persistent device state ------------------------------------------------
__device__ float    g_dist[B * B];
__device__ float    g_total;
__device__ int      g_count;
__device__ unsigned g_barcnt = 0;
__device__ volatile unsigned g_sense = 0;

// ---- threefry2x32, JAX schedule, key = [0, 42] -------------------------------
__device__ __forceinline__ uint32_t rotl32(uint32_t x, int d) {
    return __funnelshift_l(x, x, d);
}

__device__ __forceinline__ float gumbel_at(uint32_t n) {
    // counter = (0, n) since n < 384^3 < 2^32 ; key = [0, 42]
    const uint32_t k0 = 0u, k1 = 42u;
    const uint32_t k2 = k0 ^ k1 ^ 0x1BD11BDAu;
    uint32_t x0 = 0u + k0, x1 = n + k1;
#define TF_RND(r) { x0 += x1; x1 = rotl32(x1, (r)); x1 ^= x0; }
    TF_RND(13) TF_RND(15) TF_RND(26) TF_RND(6)
    x0 += k1; x1 += k2 + 1u;
    TF_RND(17) TF_RND(29) TF_RND(16) TF_RND(24)
    x0 += k2; x1 += k0 + 2u;
    TF_RND(13) TF_RND(15) TF_RND(26) TF_RND(6)
    x0 += k0; x1 += k1 + 3u;
    TF_RND(17) TF_RND(29) TF_RND(16) TF_RND(24)
    x0 += k1; x1 += k2 + 4u;
    TF_RND(13) TF_RND(15) TF_RND(26) TF_RND(6)
    x0 += k2; x1 += k0 + 5u;
#undef TF_RND
    uint32_t bits = x0 ^ x1;   // partitionable 32-bit draw
    float f = __uint_as_float((bits >> 9) | 0x3f800000u) - 1.0f;
    float u = fmaxf(TINYF, f + TINYF);
    return -logf(-logf(u));
}

// ---- sense-reversing grid barrier (all blocks resident: 144 <= 148 SMs) -----
__device__ __forceinline__ void grid_barrier() {
    __syncthreads();
    __threadfence();
    if (threadIdx.x == 0) {
        unsigned s = g_sense;
        if (atomicAdd(&g_barcnt, 1u) == gridDim.x - 1) {
            atomicExch(&g_barcnt, 0u);
            __threadfence();
            g_sense = s ^ 1u;
        } else {
            while (g_sense == s) { }
        }
    }
    __syncthreads();
}

// ---- the fused kernel --------------------------------------------------------
__global__ void __launch_bounds__(NTHR)
k_fused(const float* __restrict__ f, const int* __restrict__ labels,
        const int* __restrict__ epoch, float* __restrict__ out) {
    __shared__ float As[TILE][TILE + 1];
    __shared__ float Bs[TILE][TILE + 1];
    __shared__ int   s_lab[B];
    __shared__ int   s_pairs[1024];
    __shared__ int   s_np;
    __shared__ float s_val[16];
    __shared__ int   s_idx[16];
    __shared__ int   s_anyv[16];

    const int tid = threadIdx.x;
    const int bid = blockIdx.x;

    if (bid == 0 && tid == 0) { g_total = 0.0f; g_count = 0; }
    if (tid < B) s_lab[tid] = labels[tid];
    if (tid == 0) s_np = 0;

    // ---- phase 1: distance tile (32x32), K chunked by 32 ----
    {
        const int by = bid / 12, bx = bid % 12;
        const int i0 = by * TILE, j0 = bx * TILE;
        const int lr = tid >> 5;          // load row 0..15 (and +16)
        const int lc = tid & 31;          // load col
        const int r0 = tid >> 5;          // output rows r0 and r0+16, col c0
        const int c0 = tid & 31;
        float acc0 = 0.0f, acc1 = 0.0f;

        for (int kk = 0; kk < D; kk += TILE) {
            As[lr][lc]      = f[(i0 + lr)      * D + kk + lc];
            As[lr + 16][lc] = f[(i0 + lr + 16) * D + kk + lc];
            Bs[lr][lc]      = f[(j0 + lr)      * D + kk + lc];
            Bs[lr + 16][lc] = f[(j0 + lr + 16) * D + kk + lc];
            __syncthreads();
#pragma unroll
            for (int k2 = 0; k2 < TILE; k2++) {
                float bv = Bs[c0][k2];                 // conflict-free (pitch 33)
                float d0 = As[r0][k2] - bv;            // broadcast
                float d1 = As[r0 + 16][k2] - bv;
                acc0 += d0 * d0;
                acc1 += d1 * d1;
            }
            __syncthreads();
        }
        g_dist[(i0 + r0)      * B + j0 + c0] = sqrtf(fmaxf(acc0, 1e-11f));
        g_dist[(i0 + r0 + 16) * B + j0 + c0] = sqrtf(fmaxf(acc1, 1e-11f));
    }

    grid_barrier();

    // ---- phase 3: pair scan (384*384 == 144 * 1024 combos) ----
#pragma unroll
    for (int e = 0; e < 2; e++) {
        int idx = bid * 1024 + tid + e * NTHR;
        int i = idx / B, p = idx - i * B;
        if (p > i && s_lab[i] == s_lab[p]) {
            int slot = atomicAdd(&s_np, 1);
            s_pairs[slot] = (i << 16) | p;
        }
    }
    __syncthreads();

    // ---- per-pair gumbel argmax ----
    const bool semi_mode = (epoch[0] > 3);
    const int lane = tid & 31, w = tid >> 5;
    float bl_total = 0.0f;
    int   bl_count = 0;
    const int np = s_np;

    for (int q = 0; q < np; q++) {
        const int code = s_pairs[q];
        const int i = code >> 16, p = code & 0xffff;
        const float dpos = g_dist[i * B + p];

        float score = -3.0e38f;
        int   ix = tid;
        bool  semi = false;
        if (tid < B) {
            const int k = tid;
            const float dik = g_dist[i * B + k];
            const bool neg = (s_lab[k] != s_lab[i]);
            semi = semi_mode ? (neg && dik > dpos && dik < dpos + MARGIN) : neg;
            if (semi) {
                float base = semi_mode ? -logf(dik) : 0.0f;
                score = base + gumbel_at(((uint32_t)i * B + p) * B + k);
            }
        }
        // warp argmax, first-index tie break
#pragma unroll
        for (int off = 16; off; off >>= 1) {
            float ov = __shfl_down_sync(0xffffffffu, score, off);
            int   oi = __shfl_down_sync(0xffffffffu, ix, off);
            if (ov > score || (ov == score && oi < ix)) { score = ov; ix = oi; }
        }
        unsigned anyw = __ballot_sync(0xffffffffu, semi);
        if (lane == 0) { s_val[w] = score; s_idx[w] = ix; s_anyv[w] = (anyw != 0); }
        __syncthreads();

        if (tid == 0) {
            float bv = s_val[0]; int bi = s_idx[0]; int any = s_anyv[0];
#pragma unroll
            for (int ww = 1; ww < 16; ww++) {
                any |= s_anyv[ww];
                if (s_val[ww] > bv || (s_val[ww] == bv && s_idx[ww] < bi)) {
                    bv = s_val[ww]; bi = s_idx[ww];
                }
            }
            if (any) {
                bl_total += fmaxf(dpos - g_dist[i * B + bi] + MARGIN, 0.0f);
                bl_count += 1;
            }
        }
        __syncthreads();
    }

    if (tid == 0 && bl_count > 0) {
        atomicAdd(&g_total, bl_total);
        atomicAdd(&g_count, bl_count);
    }

    grid_barrier();

    if (bid == 0 && tid == 0) {
        int c = g_count;
        out[0] = (c > 0) ? (g_total / (float)c) : 0.0f;
    }
}

// ---- launch ------------------------------------------------------------------
extern "C" void kernel_launch(void* const* d_in, const int* in_sizes, int n_in,
                              void* d_out, int out_size) {
    const float* feat   = (const float*)d_in[0];
    const int*   labels = (const int*)d_in[1];
    const int*   epoch  = (const int*)d_in[2];
    float* out = (float*)d_out;

    k_fused<<<NBLK, NTHR>>>(feat, labels, epoch, out);
}

// round 5
// speedup vs baseline: 1.1001x; 1.0427x over previous
#include <cuda_runtime.h>
#include <cstdint>

// ---------------------------------------------------------------------------
// TripletLoss, single fused persistent kernel.
//   B=384, D=256, C=48. JAX-exact gumbel via threefry2x32 (partitionable path,
//   bits = x0^x1, key=[0,42]), evaluated on demand at semi-hard sites only.
//   Phase 1: tiled 384x384 distance matrix (12x12 tiles of 32x32, K-chunked).
//   Phase 2: grid barrier (144 blocks, single wave on 148 SMs).
//   Phase 3: per-block pair scan + gumbel argmax + accumulation.
//   Phase 4: grid barrier, block 0 writes the scalar.
// ---------------------------------------------------------------------------

#define B 384
#define D 256
#define MARGIN 0.2f
#define TINYF 1.17549435e-38f
#define NBLK 144
#define NTHR 512
#define TILE 32

// ---- persistent device state ------------------------------------------------
__device__ float    g_dist[B * B];
__device__ float    g_total;
__device__ int      g_count;
__device__ unsigned g_barcnt = 0;
__device__ volatile unsigned g_sense = 0;

// ---- threefry2x32, JAX schedule, key = [0, 42] -------------------------------
__device__ __forceinline__ uint32_t rotl32(uint32_t x, int d) {
    return __funnelshift_l(x, x, d);
}

__device__ __forceinline__ float gumbel_at(uint32_t n) {
    // counter = (0, n) since n < 384^3 < 2^32 ; key = [0, 42]
    const uint32_t k0 = 0u, k1 = 42u;
    const uint32_t k2 = k0 ^ k1 ^ 0x1BD11BDAu;
    uint32_t x0 = 0u + k0, x1 = n + k1;
#define TF_RND(r) { x0 += x1; x1 = rotl32(x1, (r)); x1 ^= x0; }
    TF_RND(13) TF_RND(15) TF_RND(26) TF_RND(6)
    x0 += k1; x1 += k2 + 1u;
    TF_RND(17) TF_RND(29) TF_RND(16) TF_RND(24)
    x0 += k2; x1 += k0 + 2u;
    TF_RND(13) TF_RND(15) TF_RND(26) TF_RND(6)
    x0 += k0; x1 += k1 + 3u;
    TF_RND(17) TF_RND(29) TF_RND(16) TF_RND(24)
    x0 += k1; x1 += k2 + 4u;
    TF_RND(13) TF_RND(15) TF_RND(26) TF_RND(6)
    x0 += k2; x1 += k0 + 5u;
#undef TF_RND
    uint32_t bits = x0 ^ x1;   // partitionable 32-bit draw
    float f = __uint_as_float((bits >> 9) | 0x3f800000u) - 1.0f;
    float u = fmaxf(TINYF, f + TINYF);
    return -logf(-logf(u));
}

// ---- sense-reversing grid barrier (all blocks resident: 144 <= 148 SMs) -----
__device__ __forceinline__ void grid_barrier() {
    __syncthreads();
    __threadfence();
    if (threadIdx.x == 0) {
        unsigned s = g_sense;
        if (atomicAdd(&g_barcnt, 1u) == gridDim.x - 1) {
            atomicExch(&g_barcnt, 0u);
            __threadfence();
            g_sense = s ^ 1u;
        } else {
            while (g_sense == s) { }
        }
    }
    __syncthreads();
}

// ---- the fused kernel --------------------------------------------------------
__global__ void __launch_bounds__(NTHR)
k_fused(const float* __restrict__ f, const int* __restrict__ labels,
        const int* __restrict__ epoch, float* __restrict__ out) {
    __shared__ float As[TILE][TILE + 1];
    __shared__ float Bs[TILE][TILE + 1];
    __shared__ int   s_lab[B];
    __shared__ int   s_pairs[1024];
    __shared__ int   s_np;
    __shared__ float s_val[16];
    __shared__ int   s_idx[16];
    __shared__ int   s_anyv[16];

    const int tid = threadIdx.x;
    const int bid = blockIdx.x;

    if (bid == 0 && tid == 0) { g_total = 0.0f; g_count = 0; }
    if (tid < B) s_lab[tid] = labels[tid];
    if (tid == 0) s_np = 0;

    // ---- phase 1: distance tile (32x32), K chunked by 32 ----
    {
        const int by = bid / 12, bx = bid % 12;
        const int i0 = by * TILE, j0 = bx * TILE;
        const int lr = tid >> 5;          // load row 0..15 (and +16)
        const int lc = tid & 31;          // load col
        const int r0 = tid >> 5;          // output rows r0 and r0+16, col c0
        const int c0 = tid & 31;
        float acc0 = 0.0f, acc1 = 0.0f;

        for (int kk = 0; kk < D; kk += TILE) {
            As[lr][lc]      = f[(i0 + lr)      * D + kk + lc];
            As[lr + 16][lc] = f[(i0 + lr + 16) * D + kk + lc];
            Bs[lr][lc]      = f[(j0 + lr)      * D + kk + lc];
            Bs[lr + 16][lc] = f[(j0 + lr + 16) * D + kk + lc];
            __syncthreads();
#pragma unroll
            for (int k2 = 0; k2 < TILE; k2++) {
                float bv = Bs[c0][k2];                 // conflict-free (pitch 33)
                float d0 = As[r0][k2] - bv;            // broadcast
                float d1 = As[r0 + 16][k2] - bv;
                acc0 += d0 * d0;
                acc1 += d1 * d1;
            }
            __syncthreads();
        }
        g_dist[(i0 + r0)      * B + j0 + c0] = sqrtf(fmaxf(acc0, 1e-11f));
        g_dist[(i0 + r0 + 16) * B + j0 + c0] = sqrtf(fmaxf(acc1, 1e-11f));
    }

    grid_barrier();

    // ---- phase 3: pair scan (384*384 == 144 * 1024 combos) ----
#pragma unroll
    for (int e = 0; e < 2; e++) {
        int idx = bid * 1024 + tid + e * NTHR;
        int i = idx / B, p = idx - i * B;
        if (p > i && s_lab[i] == s_lab[p]) {
            int slot = atomicAdd(&s_np, 1);
            s_pairs[slot] = (i << 16) | p;
        }
    }
    __syncthreads();

    // ---- per-pair gumbel argmax ----
    const bool semi_mode = (epoch[0] > 3);
    const int lane = tid & 31, w = tid >> 5;
    float bl_total = 0.0f;
    int   bl_count = 0;
    const int np = s_np;

    for (int q = 0; q < np; q++) {
        const int code = s_pairs[q];
        const int i = code >> 16, p = code & 0xffff;
        const float dpos = g_dist[i * B + p];

        float score = -3.0e38f;
        int   ix = tid;
        bool  semi = false;
        if (tid < B) {
            const int k = tid;
            const float dik = g_dist[i * B + k];
            const bool neg = (s_lab[k] != s_lab[i]);
            semi = semi_mode ? (neg && dik > dpos && dik < dpos + MARGIN) : neg;
            if (semi) {
                float base = semi_mode ? -logf(dik) : 0.0f;
                score = base + gumbel_at(((uint32_t)i * B + p) * B + k);
            }
        }
        // warp argmax, first-index tie break
#pragma unroll
        for (int off = 16; off; off >>= 1) {
            float ov = __shfl_down_sync(0xffffffffu, score, off);
            int   oi = __shfl_down_sync(0xffffffffu, ix, off);
            if (ov > score || (ov == score && oi < ix)) { score = ov; ix = oi; }
        }
        unsigned anyw = __ballot_sync(0xffffffffu, semi);
        if (lane == 0) { s_val[w] = score; s_idx[w] = ix; s_anyv[w] = (anyw != 0); }
        __syncthreads();

        if (tid == 0) {
            float bv = s_val[0]; int bi = s_idx[0]; int any = s_anyv[0];
#pragma unroll
            for (int ww = 1; ww < 16; ww++) {
                any |= s_anyv[ww];
                if (s_val[ww] > bv || (s_val[ww] == bv && s_idx[ww] < bi)) {
                    bv = s_val[ww]; bi = s_idx[ww];
                }
            }
            if (any) {
                bl_total += fmaxf(dpos - g_dist[i * B + bi] + MARGIN, 0.0f);
                bl_count += 1;
            }
        }
        __syncthreads();
    }

    if (tid == 0 && bl_count > 0) {
        atomicAdd(&g_total, bl_total);
        atomicAdd(&g_count, bl_count);
    }

    grid_barrier();

    if (bid == 0 && tid == 0) {
        int c = g_count;
        out[0] = (c > 0) ? (g_total / (float)c) : 0.0f;
    }
}

// ---- launch ------------------------------------------------------------------
extern "C" void kernel_launch(void* const* d_in, const int* in_sizes, int n_in,
                              void* d_out, int out_size) {
    const float* feat   = (const float*)d_in[0];
    const int*   labels = (const int*)d_in[1];
    const int*   epoch  = (const int*)d_in[2];
    float* out = (float*)d_out;

    k_fused<<<NBLK, NTHR>>>(feat, labels, epoch, out);
}

// round 6
// speedup vs baseline: 1.6429x; 1.4934x over previous
#include <cuda_runtime.h>
#include <cstdint>

// ---------------------------------------------------------------------------
// TripletLoss, single fused persistent kernel, warp-per-pair phase B.
//   B=384, D=256, C=48. JAX-exact gumbel via threefry2x32 (partitionable,
//   bits = x0^x1, key=[0,42]) evaluated only at semi-hard sites.
//   Phase A: pair compaction (global list) + tiled 384x384 distance matrix.
//   Grid barrier (144 blocks, single wave).
//   Phase B: one warp per (anchor,positive) pair -> argmax, block accumulate.
//   Finalize: last-done block writes scalar and resets state for replay.
// ---------------------------------------------------------------------------

#define B 384
#define D 256
#define MARGIN 0.2f
#define TINYF 1.17549435e-38f
#define NBLK 144
#define NTHR 512
#define TILE 32
#define NPAIR_MAX ((B * (B - 1)) / 2)

// ---- persistent device state (all restored to initial values each run) ----
__device__ float    g_dist[B * B];
__device__ int      g_pairlist[NPAIR_MAX];
__device__ int      g_npairs = 0;
__device__ float    g_total  = 0.0f;
__device__ int      g_count  = 0;
__device__ unsigned g_done   = 0;
__device__ unsigned g_barcnt = 0;
__device__ volatile unsigned g_sense = 0;

// ---- threefry2x32, JAX schedule, key = [0, 42] -----------------------------
__device__ __forceinline__ uint32_t rotl32(uint32_t x, int d) {
    return __funnelshift_l(x, x, d);
}

// noinline: keeps the 12x-unrolled phase-B loop small in I-cache; the call
// only executes on semi-hard lanes (~30 of 384 candidates per pair).
__device__ __noinline__ float gumbel_at(uint32_t n) {
    // counter = (0, n) since n < 384^3 < 2^32 ; key = [0, 42]
    const uint32_t k0 = 0u, k1 = 42u;
    const uint32_t k2 = k0 ^ k1 ^ 0x1BD11BDAu;
    uint32_t x0 = 0u + k0, x1 = n + k1;
#define TF_RND(r) { x0 += x1; x1 = rotl32(x1, (r)); x1 ^= x0; }
    TF_RND(13) TF_RND(15) TF_RND(26) TF_RND(6)
    x0 += k1; x1 += k2 + 1u;
    TF_RND(17) TF_RND(29) TF_RND(16) TF_RND(24)
    x0 += k2; x1 += k0 + 2u;
    TF_RND(13) TF_RND(15) TF_RND(26) TF_RND(6)
    x0 += k0; x1 += k1 + 3u;
    TF_RND(17) TF_RND(29) TF_RND(16) TF_RND(24)
    x0 += k1; x1 += k2 + 4u;
    TF_RND(13) TF_RND(15) TF_RND(26) TF_RND(6)
    x0 += k2; x1 += k0 + 5u;
#undef TF_RND
    uint32_t bits = x0 ^ x1;   // partitionable 32-bit draw
    float f = __uint_as_float((bits >> 9) | 0x3f800000u) - 1.0f;
    float u = fmaxf(TINYF, f + TINYF);
    return -logf(-logf(u));
}

// ---- sense-reversing grid barrier (144 blocks <= 148 SMs, 1/SM resident) ---
__device__ __forceinline__ void grid_barrier() {
    __syncthreads();
    __threadfence();
    if (threadIdx.x == 0) {
        unsigned s = g_sense;
        if (atomicAdd(&g_barcnt, 1u) == gridDim.x - 1) {
            atomicExch(&g_barcnt, 0u);
            __threadfence();
            g_sense = s ^ 1u;
        } else {
            while (g_sense == s) { }
        }
    }
    __syncthreads();
}

// ---- the fused kernel --------------------------------------------------------
__global__ void __launch_bounds__(NTHR)
k_fused(const float* __restrict__ f, const int* __restrict__ labels,
        const int* __restrict__ epoch, float* __restrict__ out) {
    __shared__ float As[TILE][TILE + 1];
    __shared__ float Bs[TILE][TILE + 1];
    __shared__ int   s_lab[B];
    __shared__ float s_total;
    __shared__ int   s_count;

    const int tid = threadIdx.x;
    const int bid = blockIdx.x;

    if (tid < B) s_lab[tid] = labels[tid];
    if (tid == 0) { s_total = 0.0f; s_count = 0; }
    __syncthreads();

    // ---- phase A1: pair compaction (384*384 == 144 * 1024 combos) ----
#pragma unroll
    for (int e = 0; e < 2; e++) {
        int idx = bid * 1024 + e * NTHR + tid;
        int i = idx / B, p = idx - i * B;
        if (p > i && s_lab[i] == s_lab[p]) {
            int slot = atomicAdd(&g_npairs, 1);
            g_pairlist[slot] = (i << 16) | p;
        }
    }

    // ---- phase A2: distance tile (32x32), K chunked by 32 ----
    {
        const int by = bid / 12, bx = bid % 12;
        const int i0 = by * TILE, j0 = bx * TILE;
        const int lr = tid >> 5;          // rows lr and lr+16
        const int lc = tid & 31;
        const int r0 = tid >> 5;
        const int c0 = tid & 31;
        float acc0 = 0.0f, acc1 = 0.0f;

        for (int kk = 0; kk < D; kk += TILE) {
            As[lr][lc]      = f[(i0 + lr)      * D + kk + lc];
            As[lr + 16][lc] = f[(i0 + lr + 16) * D + kk + lc];
            Bs[lr][lc]      = f[(j0 + lr)      * D + kk + lc];
            Bs[lr + 16][lc] = f[(j0 + lr + 16) * D + kk + lc];
            __syncthreads();
#pragma unroll
            for (int k2 = 0; k2 < TILE; k2++) {
                float bv = Bs[c0][k2];                 // stride-33, conflict-free
                float d0 = As[r0][k2] - bv;            // broadcast
                float d1 = As[r0 + 16][k2] - bv;
                acc0 += d0 * d0;
                acc1 += d1 * d1;
            }
            __syncthreads();
        }
        g_dist[(i0 + r0)      * B + j0 + c0] = sqrtf(fmaxf(acc0, 1e-11f));
        g_dist[(i0 + r0 + 16) * B + j0 + c0] = sqrtf(fmaxf(acc1, 1e-11f));
    }

    grid_barrier();

    // ---- phase B: one warp per pair ----
    const bool semi_mode = (epoch[0] > 3);
    const int lane  = tid & 31;
    const int gw    = bid * (NTHR / 32) + (tid >> 5);
    const int nwarp = gridDim.x * (NTHR / 32);
    const int np    = *(volatile int*)&g_npairs;

    float wsum = 0.0f;
    int   wcnt = 0;

    for (int q = gw; q < np; q += nwarp) {
        const int code = g_pairlist[q];
        const int i = code >> 16, p = code & 0xffff;
        const int li = s_lab[i];
        const float* drow = g_dist + i * B;
        const float dpos = drow[p];
        const uint32_t nbase = ((uint32_t)i * B + p) * B;

        float best = -3.0e38f;
        int   bidx = 0x7fffffff;
        bool  anyf = false;
#pragma unroll
        for (int s = 0; s < B / 32; s++) {
            const int k = s * 32 + lane;
            const float dik = drow[k];                 // coalesced 128B
            const bool neg = (s_lab[k] != li);
            const bool semi = semi_mode
                ? (neg && dik > dpos && dik < dpos + MARGIN) : neg;
            if (semi) {
                anyf = true;
                float base = semi_mode ? -logf(dik) : 0.0f;
                float sc = base + gumbel_at(nbase + k);
                if (sc > best || (sc == best && k < bidx)) { best = sc; bidx = k; }
            }
        }
        // warp argmax, first-index tie break (matches jnp.argmax)
#pragma unroll
        for (int off = 16; off; off >>= 1) {
            float ov = __shfl_down_sync(0xffffffffu, best, off);
            int   oi = __shfl_down_sync(0xffffffffu, bidx, off);
            if (ov > best || (ov == best && oi < bidx)) { best = ov; bidx = oi; }
        }
        const bool any = __any_sync(0xffffffffu, anyf);
        if (lane == 0 && any) {
            wsum += fmaxf(dpos - drow[bidx] + MARGIN, 0.0f);
            wcnt += 1;
        }
    }

    if (lane == 0 && wcnt > 0) {
        atomicAdd(&s_total, wsum);
        atomicAdd(&s_count, wcnt);
    }
    __syncthreads();
    if (tid == 0 && s_count > 0) {
        atomicAdd(&g_total, s_total);
        atomicAdd(&g_count, s_count);
    }

    // ---- finalize: last block to arrive writes the result & resets state ----
    __threadfence();
    if (tid == 0) {
        if (atomicAdd(&g_done, 1u) == gridDim.x - 1) {
            float tot = atomicAdd(&g_total, 0.0f);   // atomic read-after-fence
            int   cnt = atomicAdd(&g_count, 0);
            out[0] = (cnt > 0) ? (tot / (float)cnt) : 0.0f;
            // reset persistent state for the next graph replay
            g_total  = 0.0f;
            g_count  = 0;
            g_npairs = 0;
            __threadfence();
            atomicExch(&g_done, 0u);
        }
    }
}

// ---- launch ------------------------------------------------------------------
extern "C" void kernel_launch(void* const* d_in, const int* in_sizes, int n_in,
                              void* d_out, int out_size) {
    const float* feat   = (const float*)d_in[0];
    const int*   labels = (const int*)d_in[1];
    const int*   epoch  = (const int*)d_in[2];
    float* out = (float*)d_out;

    k_fused<<<NBLK, NTHR>>>(feat, labels, epoch, out);
}